// round 2
// baseline (speedup 1.0000x reference)
#include <cuda_runtime.h>
#include <cuda_bf16.h>

#define NN 50000
#define EE 500000

// ---------------- device scratch (no allocs allowed) ----------------
__device__ __align__(16) float g_h [NN*64];
__device__ __align__(16) float g_hn[NN*64];
__device__ __align__(16) float g_q [NN*256];
__device__ __align__(16) float g_k [NN*256];
__device__ __align__(16) float g_v [NN*256];
__device__ __align__(16) float g_s [NN*64];
__device__ __align__(16) float g_alpha[EE*4];
__device__ int   g_deg[NN];
__device__ int   g_rowptr[NN+1];
__device__ int   g_cursor[NN];
__device__ int   g_srcs[EE];

__device__ __forceinline__ float elu(float x){ return x > 0.f ? x : (__expf(x) - 1.f); }

// ---------------- CSR build ----------------
__global__ void k_zero_deg(){
    int i = blockIdx.x*blockDim.x + threadIdx.x;
    if (i < NN) g_deg[i] = 0;
}

__global__ void k_hist(const int* __restrict__ ei){
    int e = blockIdx.x*blockDim.x + threadIdx.x;
    if (e < EE) atomicAdd(&g_deg[ei[EE + e]], 1);
}

__global__ void k_scan(){
    __shared__ int wexc[32], wtot[32];
    __shared__ int s_off;
    int tid = threadIdx.x, lane = tid & 31, wid = tid >> 5;
    if (tid == 0) s_off = 0;
    __syncthreads();
    for (int base = 0; base < NN; base += 1024){
        int i = base + tid;
        int v = (i < NN) ? g_deg[i] : 0;
        int incl = v;
        #pragma unroll
        for (int d = 1; d < 32; d <<= 1){
            int t = __shfl_up_sync(0xffffffffu, incl, d);
            if (lane >= d) incl += t;
        }
        if (lane == 31) wtot[wid] = incl;
        __syncthreads();
        if (wid == 0){
            int wv = wtot[lane];
            int wi = wv;
            #pragma unroll
            for (int d = 1; d < 32; d <<= 1){
                int t = __shfl_up_sync(0xffffffffu, wi, d);
                if (lane >= d) wi += t;
            }
            wexc[lane] = wi - wv;
        }
        __syncthreads();
        int excl = s_off + wexc[wid] + incl - v;
        if (i < NN){ g_rowptr[i] = excl; g_cursor[i] = excl; }
        __syncthreads();
        if (tid == 0) s_off += wexc[31] + wtot[31];
        __syncthreads();
    }
    if (tid == 0) g_rowptr[NN] = s_off;
}

__global__ void k_fill(const int* __restrict__ ei){
    int e = blockIdx.x*blockDim.x + threadIdx.x;
    if (e < EE){
        int d = ei[EE + e];
        int p = atomicAdd(&g_cursor[d], 1);
        g_srcs[p] = ei[e];
    }
}

// ---------------- encoder: x(N,8) -> h(N,64), two ELU linears ----------------
__global__ void k_encoder(const float* __restrict__ x,
                          const float* __restrict__ w1, const float* __restrict__ b1,
                          const float* __restrict__ w2, const float* __restrict__ b2){
    __shared__ float sw1[8*64];    // [k][u]
    __shared__ float sw2[64*64];   // [k][u]
    __shared__ float sb1[64], sb2[64];
    __shared__ float st1[4][64];
    int tid = threadIdx.x;
    #pragma unroll
    for (int i = 0; i < 2; i++){
        int idx = tid + i*256;          // 0..511 over w1 (64,8)
        int u = idx >> 3, k = idx & 7;
        sw1[k*64 + u] = w1[idx];
    }
    #pragma unroll
    for (int i = 0; i < 16; i++){
        int idx = tid + i*256;
        sw2[(idx & 63)*64 + (idx >> 6)] = w2[idx];
    }
    if (tid < 64){ sb1[tid] = b1[tid]; sb2[tid] = b2[tid]; }
    __syncthreads();

    int u = tid & 63, nl = tid >> 6;
    int n0 = blockIdx.x * 64;
    for (int it = 0; it < 16; ++it){
        int n = n0 + it*4 + nl;
        float t1 = 0.f;
        if (n < NN){
            float s = sb1[u];
            #pragma unroll
            for (int k = 0; k < 8; k++) s += x[n*8 + k] * sw1[k*64 + u];
            t1 = elu(s);
        }
        st1[nl][u] = t1;
        __syncthreads();
        if (n < NN){
            float s = sb2[u];
            #pragma unroll
            for (int k = 0; k < 64; k++) s += st1[nl][k] * sw2[k*64 + u];
            g_h[n*64 + u] = elu(s);
        }
        __syncthreads();
    }
}

// ---------------- per-layer q/k/v/skip GEMM: h(N,64) @ W(64out,64in)^T tiles ----------------
// grid.x: node tiles of 64; grid.y: 13 output tiles (4 q, 4 k, 4 v, 1 skip)
__global__ void k_gemm(int pp,
                       const float* __restrict__ Wq, const float* __restrict__ bq,
                       const float* __restrict__ Wk, const float* __restrict__ bk,
                       const float* __restrict__ Wv, const float* __restrict__ bv,
                       const float* __restrict__ Ws, const float* __restrict__ bs){
    const float* hin = pp ? g_hn : g_h;
    int t = blockIdx.y;
    const float* W; const float* bias; float* out; int ldo, coff;
    if (t < 4)      { W = Wq + t*64*64;      bias = bq + t*64;      out = g_q; ldo = 256; coff = t*64; }
    else if (t < 8) { W = Wk + (t-4)*64*64;  bias = bk + (t-4)*64;  out = g_k; ldo = 256; coff = (t-4)*64; }
    else if (t <12) { W = Wv + (t-8)*64*64;  bias = bv + (t-8)*64;  out = g_v; ldo = 256; coff = (t-8)*64; }
    else            { W = Ws;                bias = bs;             out = g_s; ldo = 64;  coff = 0; }

    __shared__ float shA[64*68];   // hin transposed: [k][m], pitch 68 (16B aligned)
    __shared__ float shB[64*68];   // W   transposed: [k][n]
    int tid = threadIdx.x;
    int m0 = blockIdx.x * 64;

    #pragma unroll
    for (int i = 0; i < 4; i++){
        int idx = tid + i*256;           // 0..1023
        int row = idx >> 4;              // 0..63
        int c4  = idx & 15;              // 0..15
        float4 va = make_float4(0,0,0,0);
        if (m0 + row < NN) va = *(const float4*)&hin[(m0 + row)*64 + c4*4];
        shA[(c4*4+0)*68 + row] = va.x;
        shA[(c4*4+1)*68 + row] = va.y;
        shA[(c4*4+2)*68 + row] = va.z;
        shA[(c4*4+3)*68 + row] = va.w;
        float4 vb = *(const float4*)&W[row*64 + c4*4];
        shB[(c4*4+0)*68 + row] = vb.x;
        shB[(c4*4+1)*68 + row] = vb.y;
        shB[(c4*4+2)*68 + row] = vb.z;
        shB[(c4*4+3)*68 + row] = vb.w;
    }
    __syncthreads();

    int ty = tid >> 4, tx = tid & 15;
    float acc[4][4] = {};
    #pragma unroll 16
    for (int k = 0; k < 64; k++){
        float4 a = *(const float4*)&shA[k*68 + ty*4];
        float4 b = *(const float4*)&shB[k*68 + tx*4];
        acc[0][0] += a.x*b.x; acc[0][1] += a.x*b.y; acc[0][2] += a.x*b.z; acc[0][3] += a.x*b.w;
        acc[1][0] += a.y*b.x; acc[1][1] += a.y*b.y; acc[1][2] += a.y*b.z; acc[1][3] += a.y*b.w;
        acc[2][0] += a.z*b.x; acc[2][1] += a.z*b.y; acc[2][2] += a.z*b.z; acc[2][3] += a.z*b.w;
        acc[3][0] += a.w*b.x; acc[3][1] += a.w*b.y; acc[3][2] += a.w*b.z; acc[3][3] += a.w*b.w;
    }

    #pragma unroll
    for (int i = 0; i < 4; i++){
        int m = m0 + ty*4 + i;
        if (m < NN){
            #pragma unroll
            for (int j = 0; j < 4; j++){
                int nl = tx*4 + j;
                out[m*ldo + coff + nl] = acc[i][j] + bias[nl];
            }
        }
    }
}

// ---------------- edge kernel: per-dst warp, online softmax + weighted V agg ----------------
__global__ void k_edge(int pp){
    int gw = (blockIdx.x*blockDim.x + threadIdx.x) >> 5;
    int lane = threadIdx.x & 31;
    if (gw >= NN) return;
    int dst = gw;
    float* hout = pp ? g_h : g_hn;

    float4 q1 = *(const float4*)&g_q[dst*256 + lane*8];
    float4 q2 = *(const float4*)&g_q[dst*256 + lane*8 + 4];
    int beg = g_rowptr[dst], end = g_rowptr[dst+1];

    float m = -1e30f, ssum = 0.f;
    for (int p = beg; p < end; p++){
        int s = g_srcs[p];
        float4 k1 = *(const float4*)&g_k[s*256 + lane*8];
        float4 k2 = *(const float4*)&g_k[s*256 + lane*8 + 4];
        float d = q1.x*k1.x + q1.y*k1.y + q1.z*k1.z + q1.w*k1.w
                + q2.x*k2.x + q2.y*k2.y + q2.z*k2.z + q2.w*k2.w;
        d += __shfl_xor_sync(0xffffffffu, d, 1);
        d += __shfl_xor_sync(0xffffffffu, d, 2);
        d += __shfl_xor_sync(0xffffffffu, d, 4);
        float a = d * 0.125f;
        if ((lane & 7) == 0) g_alpha[p*4 + (lane >> 3)] = a;
        float m2 = fmaxf(m, a);
        ssum = ssum * __expf(m - m2) + __expf(a - m2);
        m = m2;
    }

    float acc[8] = {0,0,0,0,0,0,0,0};
    float inv = (end > beg) ? 1.f / ssum : 0.f;
    for (int p = beg; p < end; p++){
        int s = g_srcs[p];
        float a = g_alpha[p*4 + (lane >> 3)];
        float w = __expf(a - m) * inv;
        float4 v1 = *(const float4*)&g_v[s*256 + lane*8];
        float4 v2 = *(const float4*)&g_v[s*256 + lane*8 + 4];
        acc[0] += w*v1.x; acc[1] += w*v1.y; acc[2] += w*v1.z; acc[3] += w*v1.w;
        acc[4] += w*v2.x; acc[5] += w*v2.y; acc[6] += w*v2.z; acc[7] += w*v2.w;
    }

    #pragma unroll
    for (int j = 0; j < 8; j++){
        acc[j] += __shfl_xor_sync(0xffffffffu, acc[j], 8);
        acc[j] += __shfl_xor_sync(0xffffffffu, acc[j], 16);
    }
    if (lane < 8){
        #pragma unroll
        for (int j = 0; j < 8; j++){
            int c = lane*8 + j;
            float o = acc[j]*0.25f + g_s[dst*64 + c];
            hout[dst*64 + c] = elu(o);
        }
    }
}

// ---------------- output MLP: 64 -> 64 -> 32 -> 8 ----------------
__global__ void k_out(const float* __restrict__ w1, const float* __restrict__ b1,
                      const float* __restrict__ w2, const float* __restrict__ b2,
                      const float* __restrict__ w3, const float* __restrict__ b3,
                      float* __restrict__ out){
    __shared__ float sw1[64*64];  // [k][u]
    __shared__ float sw2[64*32];  // [k][u]
    __shared__ float sw3[32*8];   // [k][u]
    __shared__ float sb1[64], sb2[32], sb3[8];
    __shared__ float so1[4][64];
    __shared__ float so2[4][32];
    int tid = threadIdx.x;
    #pragma unroll
    for (int i = 0; i < 16; i++){
        int idx = tid + i*256;
        sw1[(idx & 63)*64 + (idx >> 6)] = w1[idx];
    }
    #pragma unroll
    for (int i = 0; i < 8; i++){
        int idx = tid + i*256;       // 0..2047, u = idx/64 (0..31), k = idx%64
        sw2[(idx & 63)*32 + (idx >> 6)] = w2[idx];
    }
    { int idx = tid; // 256 = 8*32, u = idx/32, k = idx%32
      sw3[(idx & 31)*8 + (idx >> 5)] = w3[idx]; }
    if (tid < 64) sb1[tid] = b1[tid];
    if (tid < 32) sb2[tid] = b2[tid];
    if (tid < 8)  sb3[tid] = b3[tid];
    __syncthreads();

    int u = tid & 63, nl = tid >> 6;
    int n0 = blockIdx.x * 32;
    for (int it = 0; it < 8; ++it){
        int n = n0 + it*4 + nl;
        float o1v = 0.f;
        if (n < NN){
            float s = sb1[u];
            #pragma unroll
            for (int k = 0; k < 64; k++) s += g_h[n*64 + k] * sw1[k*64 + u];
            o1v = elu(s);
        }
        so1[nl][u] = o1v;
        __syncthreads();
        if (u < 32 && n < NN){
            float s = sb2[u];
            #pragma unroll
            for (int k = 0; k < 64; k++) s += so1[nl][k] * sw2[k*32 + u];
            so2[nl][u] = elu(s);
        }
        __syncthreads();
        if (u < 8 && n < NN){
            float s = sb3[u];
            #pragma unroll
            for (int k = 0; k < 32; k++) s += so2[nl][k] * sw3[k*8 + u];
            out[n*8 + u] = s;
        }
        __syncthreads();
    }
}

// ---------------- launch ----------------
extern "C" void kernel_launch(void* const* d_in, const int* in_sizes, int n_in,
                              void* d_out, int out_size){
    const float* x   = (const float*)d_in[0];
    const int*   ei  = (const int*)d_in[1];
    const float* enc_w1 = (const float*)d_in[2];
    const float* enc_b1 = (const float*)d_in[3];
    const float* enc_w2 = (const float*)d_in[4];
    const float* enc_b2 = (const float*)d_in[5];
    const float* Wq = (const float*)d_in[6];
    const float* bq = (const float*)d_in[7];
    const float* Wk = (const float*)d_in[8];
    const float* bk = (const float*)d_in[9];
    const float* Wv = (const float*)d_in[10];
    const float* bv = (const float*)d_in[11];
    const float* Ws = (const float*)d_in[12];
    const float* bs = (const float*)d_in[13];
    const float* ow1 = (const float*)d_in[14];
    const float* ob1 = (const float*)d_in[15];
    const float* ow2 = (const float*)d_in[16];
    const float* ob2 = (const float*)d_in[17];
    const float* ow3 = (const float*)d_in[18];
    const float* ob3 = (const float*)d_in[19];
    float* out = (float*)d_out;

    // CSR build (per call: deterministic work, inputs could change)
    k_zero_deg<<<(NN+255)/256, 256>>>();
    k_hist<<<(EE+255)/256, 256>>>(ei);
    k_scan<<<1, 1024>>>();
    k_fill<<<(EE+255)/256, 256>>>(ei);

    // encoder
    k_encoder<<<(NN+63)/64, 256>>>(x, enc_w1, enc_b1, enc_w2, enc_b2);

    // 4 TransformerConv layers
    dim3 ggrid((NN+63)/64, 13);
    for (int l = 0; l < 4; l++){
        int pp = l & 1;
        k_gemm<<<ggrid, 256>>>(pp,
            Wq + l*256*64, bq + l*256,
            Wk + l*256*64, bk + l*256,
            Wv + l*256*64, bv + l*256,
            Ws + l*64*64,  bs + l*64);
        k_edge<<<(NN*32 + 255)/256, 256>>>(pp);
    }

    // output MLP (final h is in g_h after layer 3)
    k_out<<<(NN+31)/32, 256>>>(ow1, ob1, ow2, ob2, ow3, ob3, out);
}

// round 3
// speedup vs baseline: 1.4053x; 1.4053x over previous
#include <cuda_runtime.h>
#include <cuda_bf16.h>
#include <cstdint>

#define NN 50000
#define EE 500000

// ---------------- device scratch (no allocs allowed) ----------------
__device__ __align__(16) float g_h [NN*64];
__device__ __align__(16) float g_hn[NN*64];
__device__ __align__(16) float g_q [NN*256];
__device__ __align__(16) float g_k [NN*256];
__device__ __align__(16) float g_v [NN*256];
__device__ __align__(16) float g_s [NN*64];
__device__ __align__(16) float g_alpha[EE*4];
__device__ int   g_deg[NN];
__device__ int   g_rowptr[NN+1];
__device__ int   g_cursor[NN];
__device__ int   g_srcs[EE];

__device__ __forceinline__ float elu(float x){ return x > 0.f ? x : (__expf(x) - 1.f); }

__device__ __forceinline__ uint32_t f2tf32(float f){
    uint32_t o;
    asm volatile("cvt.rna.tf32.f32 %0, %1;" : "=r"(o) : "f"(f));
    return o;
}

__device__ __forceinline__ void mma_tf32(float* d, const uint32_t* a, uint32_t b0, uint32_t b1){
    asm volatile("mma.sync.aligned.m16n8k8.row.col.f32.tf32.tf32.f32 "
        "{%0,%1,%2,%3}, {%4,%5,%6,%7}, {%8,%9}, {%0,%1,%2,%3};"
        : "+f"(d[0]), "+f"(d[1]), "+f"(d[2]), "+f"(d[3])
        : "r"(a[0]), "r"(a[1]), "r"(a[2]), "r"(a[3]), "r"(b0), "r"(b1));
}

// ---------------- CSR build ----------------
__global__ void k_zero_deg(){
    int i = blockIdx.x*blockDim.x + threadIdx.x;
    if (i < NN) g_deg[i] = 0;
}

__global__ void k_hist(const int* __restrict__ ei){
    int e = blockIdx.x*blockDim.x + threadIdx.x;
    if (e < EE) atomicAdd(&g_deg[ei[EE + e]], 1);
}

__global__ void k_scan(){
    __shared__ int wexc[32], wtot[32];
    __shared__ int s_off;
    int tid = threadIdx.x, lane = tid & 31, wid = tid >> 5;
    if (tid == 0) s_off = 0;
    __syncthreads();
    for (int base = 0; base < NN; base += 1024){
        int i = base + tid;
        int v = (i < NN) ? g_deg[i] : 0;
        int incl = v;
        #pragma unroll
        for (int d = 1; d < 32; d <<= 1){
            int t = __shfl_up_sync(0xffffffffu, incl, d);
            if (lane >= d) incl += t;
        }
        if (lane == 31) wtot[wid] = incl;
        __syncthreads();
        if (wid == 0){
            int wv = wtot[lane];
            int wi = wv;
            #pragma unroll
            for (int d = 1; d < 32; d <<= 1){
                int t = __shfl_up_sync(0xffffffffu, wi, d);
                if (lane >= d) wi += t;
            }
            wexc[lane] = wi - wv;
        }
        __syncthreads();
        int excl = s_off + wexc[wid] + incl - v;
        if (i < NN){ g_rowptr[i] = excl; g_cursor[i] = excl; }
        __syncthreads();
        if (tid == 0) s_off += wexc[31] + wtot[31];
        __syncthreads();
    }
    if (tid == 0) g_rowptr[NN] = s_off;
}

__global__ void k_fill(const int* __restrict__ ei){
    int e = blockIdx.x*blockDim.x + threadIdx.x;
    if (e < EE){
        int d = ei[EE + e];
        int p = atomicAdd(&g_cursor[d], 1);
        g_srcs[p] = ei[e];
    }
}

// ---------------- encoder: x(N,8) -> h(N,64), two ELU linears ----------------
__global__ void k_encoder(const float* __restrict__ x,
                          const float* __restrict__ w1, const float* __restrict__ b1,
                          const float* __restrict__ w2, const float* __restrict__ b2){
    __shared__ float sw1[8*64];    // [k][u]
    __shared__ float sw2[64*64];   // [k][u]
    __shared__ float sb1[64], sb2[64];
    __shared__ float st1[4][64];
    int tid = threadIdx.x;
    #pragma unroll
    for (int i = 0; i < 2; i++){
        int idx = tid + i*256;          // 0..511 over w1 (64,8)
        int u = idx >> 3, k = idx & 7;
        sw1[k*64 + u] = w1[idx];
    }
    #pragma unroll
    for (int i = 0; i < 16; i++){
        int idx = tid + i*256;
        sw2[(idx & 63)*64 + (idx >> 6)] = w2[idx];
    }
    if (tid < 64){ sb1[tid] = b1[tid]; sb2[tid] = b2[tid]; }
    __syncthreads();

    int u = tid & 63, nl = tid >> 6;
    int n0 = blockIdx.x * 64;
    for (int it = 0; it < 16; ++it){
        int n = n0 + it*4 + nl;
        float t1 = 0.f;
        if (n < NN){
            float s = sb1[u];
            #pragma unroll
            for (int k = 0; k < 8; k++) s += x[n*8 + k] * sw1[k*64 + u];
            t1 = elu(s);
        }
        st1[nl][u] = t1;
        __syncthreads();
        if (n < NN){
            float s = sb2[u];
            #pragma unroll
            for (int k = 0; k < 64; k++) s += st1[nl][k] * sw2[k*64 + u];
            g_h[n*64 + u] = elu(s);
        }
        __syncthreads();
    }
}

// ---------------- per-layer q/k/v/skip GEMM via tf32 mma.sync ----------------
// grid.x: node tiles of 64; grid.y: 13 output tiles (4 q, 4 k, 4 v, 1 skip)
// Block: 256 threads = 8 warps. Warp (wm, wn): wm=wid&3 picks 16 rows, wn=wid>>2 picks 32 cols.
__global__ void k_gemm(int pp,
                       const float* __restrict__ Wq, const float* __restrict__ bq,
                       const float* __restrict__ Wk, const float* __restrict__ bk,
                       const float* __restrict__ Wv, const float* __restrict__ bv,
                       const float* __restrict__ Ws, const float* __restrict__ bs){
    const float* hin = pp ? g_hn : g_h;
    int t = blockIdx.y;
    const float* W; const float* bias; float* out; int ldo, coff;
    if (t < 4)      { W = Wq + t*64*64;      bias = bq + t*64;      out = g_q; ldo = 256; coff = t*64; }
    else if (t < 8) { W = Wk + (t-4)*64*64;  bias = bk + (t-4)*64;  out = g_k; ldo = 256; coff = (t-4)*64; }
    else if (t <12) { W = Wv + (t-8)*64*64;  bias = bv + (t-8)*64;  out = g_v; ldo = 256; coff = (t-8)*64; }
    else            { W = Ws;                bias = bs;             out = g_s; ldo = 64;  coff = 0; }

    __shared__ uint32_t sA[64*68];   // h tile, row-major [m][k], tf32 bits, pitch 68
    __shared__ uint32_t sB[64*68];   // W tile, row-major [n][k], tf32 bits
    int tid = threadIdx.x;
    int m0 = blockIdx.x * 64;

    #pragma unroll
    for (int i = 0; i < 4; i++){
        int idx = tid + i*256;           // 0..1023, 4 floats each
        int row = idx >> 4;              // 0..63
        int c4  = idx & 15;              // 0..15
        float4 va = make_float4(0,0,0,0);
        if (m0 + row < NN) va = *(const float4*)&hin[(m0 + row)*64 + c4*4];
        sA[row*68 + c4*4+0] = f2tf32(va.x);
        sA[row*68 + c4*4+1] = f2tf32(va.y);
        sA[row*68 + c4*4+2] = f2tf32(va.z);
        sA[row*68 + c4*4+3] = f2tf32(va.w);
        float4 vb = *(const float4*)&W[row*64 + c4*4];
        sB[row*68 + c4*4+0] = f2tf32(vb.x);
        sB[row*68 + c4*4+1] = f2tf32(vb.y);
        sB[row*68 + c4*4+2] = f2tf32(vb.z);
        sB[row*68 + c4*4+3] = f2tf32(vb.w);
    }
    __syncthreads();

    int wid = tid >> 5, lane = tid & 31;
    int wm = wid & 3, wn = wid >> 2;
    int g = lane >> 2, t4 = lane & 3;

    float acc[4][4] = {};   // 4 n-tiles of 8 cols each

    const uint32_t* pa = &sA[(wm*16 + g)*68 + t4];   // a0 base; a1 at +8*68; a2 at +4; a3 at +8*68+4
    const uint32_t* pb = &sB[(wn*32 + g)*68 + t4];   // per n-tile: + nt*8*68; b1 at +4

    #pragma unroll
    for (int kc = 0; kc < 8; kc++){
        uint32_t a[4];
        a[0] = pa[kc*8];
        a[1] = pa[8*68 + kc*8];
        a[2] = pa[kc*8 + 4];
        a[3] = pa[8*68 + kc*8 + 4];
        #pragma unroll
        for (int nt = 0; nt < 4; nt++){
            uint32_t b0 = pb[nt*8*68 + kc*8];
            uint32_t b1 = pb[nt*8*68 + kc*8 + 4];
            mma_tf32(acc[nt], a, b0, b1);
        }
    }

    int row0 = m0 + wm*16 + g;
    #pragma unroll
    for (int nt = 0; nt < 4; nt++){
        int col = wn*32 + nt*8 + t4*2;
        float bz0 = bias[col], bz1 = bias[col+1];
        if (row0 < NN){
            out[row0*ldo + coff + col]     = acc[nt][0] + bz0;
            out[row0*ldo + coff + col + 1] = acc[nt][1] + bz1;
        }
        if (row0 + 8 < NN){
            out[(row0+8)*ldo + coff + col]     = acc[nt][2] + bz0;
            out[(row0+8)*ldo + coff + col + 1] = acc[nt][3] + bz1;
        }
    }
}

// ---------------- edge kernel: per-dst warp, online softmax + weighted V agg ----------------
__global__ void k_edge(int pp){
    int gw = (blockIdx.x*blockDim.x + threadIdx.x) >> 5;
    int lane = threadIdx.x & 31;
    if (gw >= NN) return;
    int dst = gw;
    float* hout = pp ? g_h : g_hn;

    float4 q1 = *(const float4*)&g_q[dst*256 + lane*8];
    float4 q2 = *(const float4*)&g_q[dst*256 + lane*8 + 4];
    int beg = g_rowptr[dst], end = g_rowptr[dst+1];

    float m = -1e30f, ssum = 0.f;
    for (int p = beg; p < end; p++){
        int s = g_srcs[p];
        float4 k1 = *(const float4*)&g_k[s*256 + lane*8];
        float4 k2 = *(const float4*)&g_k[s*256 + lane*8 + 4];
        float d = q1.x*k1.x + q1.y*k1.y + q1.z*k1.z + q1.w*k1.w
                + q2.x*k2.x + q2.y*k2.y + q2.z*k2.z + q2.w*k2.w;
        d += __shfl_xor_sync(0xffffffffu, d, 1);
        d += __shfl_xor_sync(0xffffffffu, d, 2);
        d += __shfl_xor_sync(0xffffffffu, d, 4);
        float a = d * 0.125f;
        if ((lane & 7) == 0) g_alpha[p*4 + (lane >> 3)] = a;
        float m2 = fmaxf(m, a);
        ssum = ssum * __expf(m - m2) + __expf(a - m2);
        m = m2;
    }

    float acc[8] = {0,0,0,0,0,0,0,0};
    float inv = (end > beg) ? 1.f / ssum : 0.f;
    for (int p = beg; p < end; p++){
        int s = g_srcs[p];
        float a = g_alpha[p*4 + (lane >> 3)];
        float w = __expf(a - m) * inv;
        float4 v1 = *(const float4*)&g_v[s*256 + lane*8];
        float4 v2 = *(const float4*)&g_v[s*256 + lane*8 + 4];
        acc[0] += w*v1.x; acc[1] += w*v1.y; acc[2] += w*v1.z; acc[3] += w*v1.w;
        acc[4] += w*v2.x; acc[5] += w*v2.y; acc[6] += w*v2.z; acc[7] += w*v2.w;
    }

    #pragma unroll
    for (int j = 0; j < 8; j++){
        acc[j] += __shfl_xor_sync(0xffffffffu, acc[j], 8);
        acc[j] += __shfl_xor_sync(0xffffffffu, acc[j], 16);
    }
    if (lane < 8){
        #pragma unroll
        for (int j = 0; j < 8; j++){
            int c = lane*8 + j;
            float o = acc[j]*0.25f + g_s[dst*64 + c];
            hout[dst*64 + c] = elu(o);
        }
    }
}

// ---------------- output MLP: 64 -> 64 -> 32 -> 8 ----------------
__global__ void k_out(const float* __restrict__ w1, const float* __restrict__ b1,
                      const float* __restrict__ w2, const float* __restrict__ b2,
                      const float* __restrict__ w3, const float* __restrict__ b3,
                      float* __restrict__ out){
    __shared__ float sw1[64*64];  // [k][u]
    __shared__ float sw2[64*32];  // [k][u]
    __shared__ float sw3[32*8];   // [k][u]
    __shared__ float sb1[64], sb2[32], sb3[8];
    __shared__ float so1[4][64];
    __shared__ float so2[4][32];
    int tid = threadIdx.x;
    #pragma unroll
    for (int i = 0; i < 16; i++){
        int idx = tid + i*256;
        sw1[(idx & 63)*64 + (idx >> 6)] = w1[idx];
    }
    #pragma unroll
    for (int i = 0; i < 8; i++){
        int idx = tid + i*256;       // 0..2047, u = idx/64 (0..31), k = idx%64
        sw2[(idx & 63)*32 + (idx >> 6)] = w2[idx];
    }
    { int idx = tid; // 256 = 8*32, u = idx/32, k = idx%32
      sw3[(idx & 31)*8 + (idx >> 5)] = w3[idx]; }
    if (tid < 64) sb1[tid] = b1[tid];
    if (tid < 32) sb2[tid] = b2[tid];
    if (tid < 8)  sb3[tid] = b3[tid];
    __syncthreads();

    int u = tid & 63, nl = tid >> 6;
    int n0 = blockIdx.x * 32;
    for (int it = 0; it < 8; ++it){
        int n = n0 + it*4 + nl;
        float o1v = 0.f;
        if (n < NN){
            float s = sb1[u];
            #pragma unroll
            for (int k = 0; k < 64; k++) s += g_h[n*64 + k] * sw1[k*64 + u];
            o1v = elu(s);
        }
        so1[nl][u] = o1v;
        __syncthreads();
        if (u < 32 && n < NN){
            float s = sb2[u];
            #pragma unroll
            for (int k = 0; k < 64; k++) s += so1[nl][k] * sw2[k*32 + u];
            so2[nl][u] = elu(s);
        }
        __syncthreads();
        if (u < 8 && n < NN){
            float s = sb3[u];
            #pragma unroll
            for (int k = 0; k < 32; k++) s += so2[nl][k] * sw3[k*8 + u];
            out[n*8 + u] = s;
        }
        __syncthreads();
    }
}

// ---------------- launch ----------------
extern "C" void kernel_launch(void* const* d_in, const int* in_sizes, int n_in,
                              void* d_out, int out_size){
    const float* x   = (const float*)d_in[0];
    const int*   ei  = (const int*)d_in[1];
    const float* enc_w1 = (const float*)d_in[2];
    const float* enc_b1 = (const float*)d_in[3];
    const float* enc_w2 = (const float*)d_in[4];
    const float* enc_b2 = (const float*)d_in[5];
    const float* Wq = (const float*)d_in[6];
    const float* bq = (const float*)d_in[7];
    const float* Wk = (const float*)d_in[8];
    const float* bk = (const float*)d_in[9];
    const float* Wv = (const float*)d_in[10];
    const float* bv = (const float*)d_in[11];
    const float* Ws = (const float*)d_in[12];
    const float* bs = (const float*)d_in[13];
    const float* ow1 = (const float*)d_in[14];
    const float* ob1 = (const float*)d_in[15];
    const float* ow2 = (const float*)d_in[16];
    const float* ob2 = (const float*)d_in[17];
    const float* ow3 = (const float*)d_in[18];
    const float* ob3 = (const float*)d_in[19];
    float* out = (float*)d_out;

    // CSR build (per call: deterministic work, inputs could change)
    k_zero_deg<<<(NN+255)/256, 256>>>();
    k_hist<<<(EE+255)/256, 256>>>(ei);
    k_scan<<<1, 1024>>>();
    k_fill<<<(EE+255)/256, 256>>>(ei);

    // encoder
    k_encoder<<<(NN+63)/64, 256>>>(x, enc_w1, enc_b1, enc_w2, enc_b2);

    // 4 TransformerConv layers
    dim3 ggrid((NN+63)/64, 13);
    for (int l = 0; l < 4; l++){
        int pp = l & 1;
        k_gemm<<<ggrid, 256>>>(pp,
            Wq + l*256*64, bq + l*256,
            Wk + l*256*64, bk + l*256,
            Wv + l*256*64, bv + l*256,
            Ws + l*64*64,  bs + l*64);
        k_edge<<<(NN*32 + 255)/256, 256>>>(pp);
    }

    // output MLP (final h is in g_h after layer 3)
    k_out<<<(NN+31)/32, 256>>>(ow1, ob1, ow2, ob2, ow3, ob3, out);
}

// round 4
// speedup vs baseline: 1.7121x; 1.2183x over previous
#include <cuda_runtime.h>
#include <cuda_bf16.h>
#include <cuda_fp16.h>
#include <cstdint>

#define NN 50000
#define EE 500000

// ---------------- device scratch (no allocs allowed) ----------------
__device__ __align__(16) float  g_h [NN*64];
__device__ __align__(16) float  g_hn[NN*64];
__device__ __align__(16) float  g_q [NN*256];
__device__ __align__(16) __half g_k16[NN*256];
__device__ __align__(16) __half g_v16[NN*256];
__device__ __align__(16) float  g_s [NN*64];
__device__ int   g_deg[NN];
__device__ int   g_rowptr[NN+1];
__device__ int   g_cursor[NN];
__device__ int   g_srcs[EE];

__device__ __forceinline__ float elu(float x){ return x > 0.f ? x : (__expf(x) - 1.f); }

__device__ __forceinline__ uint32_t f2tf32(float f){
    uint32_t o;
    asm volatile("cvt.rna.tf32.f32 %0, %1;" : "=r"(o) : "f"(f));
    return o;
}

__device__ __forceinline__ void mma_tf32(float* d, const uint32_t* a, uint32_t b0, uint32_t b1){
    asm volatile("mma.sync.aligned.m16n8k8.row.col.f32.tf32.tf32.f32 "
        "{%0,%1,%2,%3}, {%4,%5,%6,%7}, {%8,%9}, {%0,%1,%2,%3};"
        : "+f"(d[0]), "+f"(d[1]), "+f"(d[2]), "+f"(d[3])
        : "r"(a[0]), "r"(a[1]), "r"(a[2]), "r"(a[3]), "r"(b0), "r"(b1));
}

// ---------------- CSR build ----------------
__global__ void k_zero_deg(){
    int i = blockIdx.x*blockDim.x + threadIdx.x;
    if (i < NN) g_deg[i] = 0;
}

__global__ void k_hist(const int* __restrict__ ei){
    int e = blockIdx.x*blockDim.x + threadIdx.x;
    if (e < EE) atomicAdd(&g_deg[ei[EE + e]], 1);
}

__global__ void k_scan(){
    __shared__ int wexc[32], wtot[32];
    __shared__ int s_off;
    int tid = threadIdx.x, lane = tid & 31, wid = tid >> 5;
    if (tid == 0) s_off = 0;
    __syncthreads();
    for (int base = 0; base < NN; base += 1024){
        int i = base + tid;
        int v = (i < NN) ? g_deg[i] : 0;
        int incl = v;
        #pragma unroll
        for (int d = 1; d < 32; d <<= 1){
            int t = __shfl_up_sync(0xffffffffu, incl, d);
            if (lane >= d) incl += t;
        }
        if (lane == 31) wtot[wid] = incl;
        __syncthreads();
        if (wid == 0){
            int wv = wtot[lane];
            int wi = wv;
            #pragma unroll
            for (int d = 1; d < 32; d <<= 1){
                int t = __shfl_up_sync(0xffffffffu, wi, d);
                if (lane >= d) wi += t;
            }
            wexc[lane] = wi - wv;
        }
        __syncthreads();
        int excl = s_off + wexc[wid] + incl - v;
        if (i < NN){ g_rowptr[i] = excl; g_cursor[i] = excl; }
        __syncthreads();
        if (tid == 0) s_off += wexc[31] + wtot[31];
        __syncthreads();
    }
    if (tid == 0) g_rowptr[NN] = s_off;
}

__global__ void k_fill(const int* __restrict__ ei){
    int e = blockIdx.x*blockDim.x + threadIdx.x;
    if (e < EE){
        int d = ei[EE + e];
        int p = atomicAdd(&g_cursor[d], 1);
        g_srcs[p] = ei[e];
    }
}

// ---------------- encoder: x(N,8) -> h(N,64), two ELU linears ----------------
__global__ void k_encoder(const float* __restrict__ x,
                          const float* __restrict__ w1, const float* __restrict__ b1,
                          const float* __restrict__ w2, const float* __restrict__ b2){
    __shared__ float sw1[8*64];    // [k][u]
    __shared__ float sw2[64*64];   // [k][u]
    __shared__ float sb1[64], sb2[64];
    __shared__ float st1[4][64];
    int tid = threadIdx.x;
    #pragma unroll
    for (int i = 0; i < 2; i++){
        int idx = tid + i*256;          // 0..511 over w1 (64,8)
        int u = idx >> 3, k = idx & 7;
        sw1[k*64 + u] = w1[idx];
    }
    #pragma unroll
    for (int i = 0; i < 16; i++){
        int idx = tid + i*256;
        sw2[(idx & 63)*64 + (idx >> 6)] = w2[idx];
    }
    if (tid < 64){ sb1[tid] = b1[tid]; sb2[tid] = b2[tid]; }
    __syncthreads();

    int u = tid & 63, nl = tid >> 6;
    int n0 = blockIdx.x * 64;
    for (int it = 0; it < 16; ++it){
        int n = n0 + it*4 + nl;
        float t1 = 0.f;
        if (n < NN){
            float s = sb1[u];
            #pragma unroll
            for (int k = 0; k < 8; k++) s += x[n*8 + k] * sw1[k*64 + u];
            t1 = elu(s);
        }
        st1[nl][u] = t1;
        __syncthreads();
        if (n < NN){
            float s = sb2[u];
            #pragma unroll
            for (int k = 0; k < 64; k++) s += st1[nl][k] * sw2[k*64 + u];
            g_h[n*64 + u] = elu(s);
        }
        __syncthreads();
    }
}

// ---------------- per-layer q/k/v/skip GEMM via tf32 mma.sync ----------------
// grid.x: node tiles of 64; grid.y: 13 output tiles (4 q, 4 k, 4 v, 1 skip)
// q and skip written fp32; k and v written fp16 (half2) for the edge phase.
__global__ void k_gemm(int pp,
                       const float* __restrict__ Wq, const float* __restrict__ bq,
                       const float* __restrict__ Wk, const float* __restrict__ bk,
                       const float* __restrict__ Wv, const float* __restrict__ bv,
                       const float* __restrict__ Ws, const float* __restrict__ bs){
    const float* hin = pp ? g_hn : g_h;
    int t = blockIdx.y;
    const float* W; const float* bias; int coff;
    if (t < 4)      { W = Wq + t*64*64;      bias = bq + t*64;      coff = t*64; }
    else if (t < 8) { W = Wk + (t-4)*64*64;  bias = bk + (t-4)*64;  coff = (t-4)*64; }
    else if (t <12) { W = Wv + (t-8)*64*64;  bias = bv + (t-8)*64;  coff = (t-8)*64; }
    else            { W = Ws;                bias = bs;             coff = 0; }

    __shared__ uint32_t sA[64*68];   // h tile, row-major [m][k], tf32 bits, pitch 68
    __shared__ uint32_t sB[64*68];   // W tile, row-major [n][k], tf32 bits
    int tid = threadIdx.x;
    int m0 = blockIdx.x * 64;

    #pragma unroll
    for (int i = 0; i < 4; i++){
        int idx = tid + i*256;           // 0..1023, 4 floats each
        int row = idx >> 4;              // 0..63
        int c4  = idx & 15;              // 0..15
        float4 va = make_float4(0,0,0,0);
        if (m0 + row < NN) va = *(const float4*)&hin[(m0 + row)*64 + c4*4];
        uint4 ua;
        ua.x = f2tf32(va.x); ua.y = f2tf32(va.y); ua.z = f2tf32(va.z); ua.w = f2tf32(va.w);
        *(uint4*)&sA[row*68 + c4*4] = ua;
        float4 vb = *(const float4*)&W[row*64 + c4*4];
        uint4 ub;
        ub.x = f2tf32(vb.x); ub.y = f2tf32(vb.y); ub.z = f2tf32(vb.z); ub.w = f2tf32(vb.w);
        *(uint4*)&sB[row*68 + c4*4] = ub;
    }
    __syncthreads();

    int wid = tid >> 5, lane = tid & 31;
    int wm = wid & 3, wn = wid >> 2;
    int g = lane >> 2, t4 = lane & 3;

    float acc[4][4] = {};   // 4 n-tiles of 8 cols each

    const uint32_t* pa = &sA[(wm*16 + g)*68 + t4];
    const uint32_t* pb = &sB[(wn*32 + g)*68 + t4];

    #pragma unroll
    for (int kc = 0; kc < 8; kc++){
        uint32_t a[4];
        a[0] = pa[kc*8];
        a[1] = pa[8*68 + kc*8];
        a[2] = pa[kc*8 + 4];
        a[3] = pa[8*68 + kc*8 + 4];
        #pragma unroll
        for (int nt = 0; nt < 4; nt++){
            uint32_t b0 = pb[nt*8*68 + kc*8];
            uint32_t b1 = pb[nt*8*68 + kc*8 + 4];
            mma_tf32(acc[nt], a, b0, b1);
        }
    }

    int row0 = m0 + wm*16 + g;
    if (t >= 4 && t < 12){
        __half* o16 = (t < 8) ? g_k16 : g_v16;
        #pragma unroll
        for (int nt = 0; nt < 4; nt++){
            int col = wn*32 + nt*8 + t4*2;
            float bz0 = bias[col], bz1 = bias[col+1];
            if (row0 < NN)
                *(__half2*)&o16[row0*256 + coff + col] = __floats2half2_rn(acc[nt][0] + bz0, acc[nt][1] + bz1);
            if (row0 + 8 < NN)
                *(__half2*)&o16[(row0+8)*256 + coff + col] = __floats2half2_rn(acc[nt][2] + bz0, acc[nt][3] + bz1);
        }
    } else {
        float* outp = (t < 4) ? g_q : g_s;
        int ldo = (t < 4) ? 256 : 64;
        #pragma unroll
        for (int nt = 0; nt < 4; nt++){
            int col = wn*32 + nt*8 + t4*2;
            float bz0 = bias[col], bz1 = bias[col+1];
            if (row0 < NN){
                outp[row0*ldo + coff + col]     = acc[nt][0] + bz0;
                outp[row0*ldo + coff + col + 1] = acc[nt][1] + bz1;
            }
            if (row0 + 8 < NN){
                outp[(row0+8)*ldo + coff + col]     = acc[nt][2] + bz0;
                outp[(row0+8)*ldo + coff + col + 1] = acc[nt][3] + bz1;
            }
        }
    }
}

// ---------------- edge kernel: per-dst warp, single-pass online softmax + V agg ----------------
__global__ void k_edge(int pp){
    int gw = (blockIdx.x*blockDim.x + threadIdx.x) >> 5;
    int lane = threadIdx.x & 31;
    if (gw >= NN) return;
    int dst = gw;
    float* hout = pp ? g_h : g_hn;

    float4 q1 = *(const float4*)&g_q[dst*256 + lane*8];
    float4 q2 = *(const float4*)&g_q[dst*256 + lane*8 + 4];
    int beg = g_rowptr[dst], end = g_rowptr[dst+1];

    float m = -1e30f, ssum = 0.f;
    float acc[8] = {0,0,0,0,0,0,0,0};

    for (int p = beg; p < end; p++){
        int s = g_srcs[p];
        uint4 kr = *(const uint4*)&g_k16[s*256 + lane*8];
        uint4 vr = *(const uint4*)&g_v16[s*256 + lane*8];
        float2 k0 = __half22float2(*(__half2*)&kr.x);
        float2 k1 = __half22float2(*(__half2*)&kr.y);
        float2 k2 = __half22float2(*(__half2*)&kr.z);
        float2 k3 = __half22float2(*(__half2*)&kr.w);
        float d = q1.x*k0.x + q1.y*k0.y + q1.z*k1.x + q1.w*k1.y
                + q2.x*k2.x + q2.y*k2.y + q2.z*k3.x + q2.w*k3.y;
        d += __shfl_xor_sync(0xffffffffu, d, 1);
        d += __shfl_xor_sync(0xffffffffu, d, 2);
        d += __shfl_xor_sync(0xffffffffu, d, 4);
        float a = d * 0.125f;
        float m2 = fmaxf(m, a);
        float scale = __expf(m - m2);
        float e = __expf(a - m2);
        ssum = ssum * scale + e;
        m = m2;
        float2 v0 = __half22float2(*(__half2*)&vr.x);
        float2 v1 = __half22float2(*(__half2*)&vr.y);
        float2 v2 = __half22float2(*(__half2*)&vr.z);
        float2 v3 = __half22float2(*(__half2*)&vr.w);
        acc[0] = acc[0]*scale + e*v0.x; acc[1] = acc[1]*scale + e*v0.y;
        acc[2] = acc[2]*scale + e*v1.x; acc[3] = acc[3]*scale + e*v1.y;
        acc[4] = acc[4]*scale + e*v2.x; acc[5] = acc[5]*scale + e*v2.y;
        acc[6] = acc[6]*scale + e*v3.x; acc[7] = acc[7]*scale + e*v3.y;
    }

    float inv = (end > beg) ? 1.f / ssum : 0.f;
    #pragma unroll
    for (int j = 0; j < 8; j++){
        float aj = acc[j] * inv;
        aj += __shfl_xor_sync(0xffffffffu, aj, 8);
        aj += __shfl_xor_sync(0xffffffffu, aj, 16);
        acc[j] = aj;
    }
    if (lane < 8){
        #pragma unroll
        for (int j = 0; j < 8; j++){
            int c = lane*8 + j;
            float o = acc[j]*0.25f + g_s[dst*64 + c];
            hout[dst*64 + c] = elu(o);
        }
    }
}

// ---------------- output MLP: 64 -> 64 -> 32 -> 8 ----------------
__global__ void k_out(const float* __restrict__ w1, const float* __restrict__ b1,
                      const float* __restrict__ w2, const float* __restrict__ b2,
                      const float* __restrict__ w3, const float* __restrict__ b3,
                      float* __restrict__ out){
    __shared__ float sw1[64*64];  // [k][u]
    __shared__ float sw2[64*32];  // [k][u]
    __shared__ float sw3[32*8];   // [k][u]
    __shared__ float sb1[64], sb2[32], sb3[8];
    __shared__ float so1[4][64];
    __shared__ float so2[4][32];
    int tid = threadIdx.x;
    #pragma unroll
    for (int i = 0; i < 16; i++){
        int idx = tid + i*256;
        sw1[(idx & 63)*64 + (idx >> 6)] = w1[idx];
    }
    #pragma unroll
    for (int i = 0; i < 8; i++){
        int idx = tid + i*256;
        sw2[(idx & 63)*32 + (idx >> 6)] = w2[idx];
    }
    { int idx = tid;
      sw3[(idx & 31)*8 + (idx >> 5)] = w3[idx]; }
    if (tid < 64) sb1[tid] = b1[tid];
    if (tid < 32) sb2[tid] = b2[tid];
    if (tid < 8)  sb3[tid] = b3[tid];
    __syncthreads();

    int u = tid & 63, nl = tid >> 6;
    int n0 = blockIdx.x * 32;
    for (int it = 0; it < 8; ++it){
        int n = n0 + it*4 + nl;
        float o1v = 0.f;
        if (n < NN){
            float s = sb1[u];
            #pragma unroll
            for (int k = 0; k < 64; k++) s += g_h[n*64 + k] * sw1[k*64 + u];
            o1v = elu(s);
        }
        so1[nl][u] = o1v;
        __syncthreads();
        if (u < 32 && n < NN){
            float s = sb2[u];
            #pragma unroll
            for (int k = 0; k < 64; k++) s += so1[nl][k] * sw2[k*32 + u];
            so2[nl][u] = elu(s);
        }
        __syncthreads();
        if (u < 8 && n < NN){
            float s = sb3[u];
            #pragma unroll
            for (int k = 0; k < 32; k++) s += so2[nl][k] * sw3[k*8 + u];
            out[n*8 + u] = s;
        }
        __syncthreads();
    }
}

// ---------------- launch ----------------
extern "C" void kernel_launch(void* const* d_in, const int* in_sizes, int n_in,
                              void* d_out, int out_size){
    const float* x   = (const float*)d_in[0];
    const int*   ei  = (const int*)d_in[1];
    const float* enc_w1 = (const float*)d_in[2];
    const float* enc_b1 = (const float*)d_in[3];
    const float* enc_w2 = (const float*)d_in[4];
    const float* enc_b2 = (const float*)d_in[5];
    const float* Wq = (const float*)d_in[6];
    const float* bq = (const float*)d_in[7];
    const float* Wk = (const float*)d_in[8];
    const float* bk = (const float*)d_in[9];
    const float* Wv = (const float*)d_in[10];
    const float* bv = (const float*)d_in[11];
    const float* Ws = (const float*)d_in[12];
    const float* bs = (const float*)d_in[13];
    const float* ow1 = (const float*)d_in[14];
    const float* ob1 = (const float*)d_in[15];
    const float* ow2 = (const float*)d_in[16];
    const float* ob2 = (const float*)d_in[17];
    const float* ow3 = (const float*)d_in[18];
    const float* ob3 = (const float*)d_in[19];
    float* out = (float*)d_out;

    // CSR build
    k_zero_deg<<<(NN+255)/256, 256>>>();
    k_hist<<<(EE+255)/256, 256>>>(ei);
    k_scan<<<1, 1024>>>();
    k_fill<<<(EE+255)/256, 256>>>(ei);

    // encoder
    k_encoder<<<(NN+63)/64, 256>>>(x, enc_w1, enc_b1, enc_w2, enc_b2);

    // 4 TransformerConv layers
    dim3 ggrid((NN+63)/64, 13);
    for (int l = 0; l < 4; l++){
        int pp = l & 1;
        k_gemm<<<ggrid, 256>>>(pp,
            Wq + l*256*64, bq + l*256,
            Wk + l*256*64, bk + l*256,
            Wv + l*256*64, bv + l*256,
            Ws + l*64*64,  bs + l*64);
        k_edge<<<(NN*32 + 255)/256, 256>>>(pp);
    }

    // output MLP (final h is in g_h after layer 3)
    k_out<<<(NN+31)/32, 256>>>(ow1, ob1, ow2, ob2, ow3, ob3, out);
}